// round 3
// baseline (speedup 1.0000x reference)
#include <cuda_runtime.h>

#define N_NODES 100000
#define N_EDGES 1600000
#define NEG_SLOPE 0.2f
#define BN_EPS 1e-5f

// ---------------- scratch (device globals; no allocation allowed) ----------------
__device__ float4 g_h[N_NODES * 64];        // projected feats [N,256] as float4
__device__ float4 g_res[N_NODES * 64];      // residual proj   [N,256]
__device__ float4 g_el[N_NODES];            // [N,4]
__device__ float4 g_er[N_NODES];            // [N,4]
__device__ float4 g_w[N_EDGES];             // exp(leaky(e)) per edge [E,4]
__device__ float4 g_wsorted[N_EDGES];       // dst-sorted weights
__device__ int    g_srcsorted[N_EDGES];     // dst-sorted src ids
__device__ int    g_deg[N_NODES];
__device__ int    g_rowstart[N_NODES];
__device__ int    g_cursor[N_NODES];
__device__ float4 g_outpre[N_NODES * 16];   // pre-BN output [N,64]
__device__ float  g_bnsum[64];
__device__ float  g_bnsq[64];
__device__ int    g_blocksums[128];
__device__ int    g_blockoff[128];
__device__ float  g_scale[64];
__device__ float  g_shift[64];

// ---------------- kernels ----------------

__global__ void zero_kernel() {
    int i = blockIdx.x * blockDim.x + threadIdx.x;
    int stride = gridDim.x * blockDim.x;
    for (int idx = i; idx < N_NODES; idx += stride) { g_deg[idx] = 0; g_cursor[idx] = 0; }
    if (i < 64) { g_bnsum[i] = 0.f; g_bnsq[i] = 0.f; }
}

// C[N,512] = feats[N,128] @ [fc_w;res_w]^T, classic 128x128x8 SGEMM, 8x8 per thread.
__global__ __launch_bounds__(256) void gemm_kernel(const float* __restrict__ feats,
                                                   const float* __restrict__ fc_w,
                                                   const float* __restrict__ res_w) {
    __shared__ float As[8][128];
    __shared__ float Bs[8][128];
    int bm = blockIdx.x, bn = blockIdx.y;           // bn 0..3; 0,1->fc_w, 2,3->res_w
    const float* W = (bn < 2) ? fc_w : res_w;
    int jbase = (bn & 1) * 128;
    int t = threadIdx.x;
    int ty = t >> 4, tx = t & 15;
    float acc[8][8];
#pragma unroll
    for (int i = 0; i < 8; i++)
#pragma unroll
        for (int j = 0; j < 8; j++) acc[i][j] = 0.f;

    int arow = t >> 1;
    int ac4 = (t & 1) * 4;
    long grow = (long)bm * 128 + arow;
    bool ok = grow < N_NODES;
    const float* ap = feats + grow * 128 + ac4;
    const float* bp = W + (long)(jbase + arow) * 128 + ac4;

    for (int k0 = 0; k0 < 128; k0 += 8) {
        float4 av = ok ? *(const float4*)(ap + k0) : make_float4(0, 0, 0, 0);
        float4 bv = *(const float4*)(bp + k0);
        As[ac4 + 0][arow] = av.x; As[ac4 + 1][arow] = av.y;
        As[ac4 + 2][arow] = av.z; As[ac4 + 3][arow] = av.w;
        Bs[ac4 + 0][arow] = bv.x; Bs[ac4 + 1][arow] = bv.y;
        Bs[ac4 + 2][arow] = bv.z; Bs[ac4 + 3][arow] = bv.w;
        __syncthreads();
#pragma unroll
        for (int k = 0; k < 8; k++) {
            float a[8], b[8];
            *(float4*)(a)     = *(const float4*)(&As[k][ty * 8]);
            *(float4*)(a + 4) = *(const float4*)(&As[k][ty * 8 + 4]);
            *(float4*)(b)     = *(const float4*)(&Bs[k][tx * 8]);
            *(float4*)(b + 4) = *(const float4*)(&Bs[k][tx * 8 + 4]);
#pragma unroll
            for (int i = 0; i < 8; i++)
#pragma unroll
                for (int j = 0; j < 8; j++) acc[i][j] += a[i] * b[j];
        }
        __syncthreads();
    }

    float* hout = (float*)g_h;
    float* rout = (float*)g_res;
    int jcol = jbase + tx * 8;
#pragma unroll
    for (int i = 0; i < 8; i++) {
        long m = (long)bm * 128 + ty * 8 + i;
        if (m < N_NODES) {
            float* dstp = ((bn < 2) ? hout : rout) + m * 256 + jcol;
            *(float4*)dstp       = make_float4(acc[i][0], acc[i][1], acc[i][2], acc[i][3]);
            *(float4*)(dstp + 4) = make_float4(acc[i][4], acc[i][5], acc[i][6], acc[i][7]);
        }
    }
}

// el/er: one warp per node, dot(h[node], attn) per head.
__global__ void attn_kernel(const float* __restrict__ attn_l, const float* __restrict__ attn_r) {
    int warp = (blockIdx.x * blockDim.x + threadIdx.x) >> 5;
    int lane = threadIdx.x & 31;
    int nw = (gridDim.x * blockDim.x) >> 5;
    const float* h = (const float*)g_h;
    for (int node = warp; node < N_NODES; node += nw) {
        float el[4] = {0, 0, 0, 0}, er[4] = {0, 0, 0, 0};
#pragma unroll
        for (int g = 0; g < 8; g++) {
            int c = g * 32 + lane;
            float hv = h[(long)node * 256 + c];
            el[g >> 1] += hv * attn_l[c];
            er[g >> 1] += hv * attn_r[c];
        }
#pragma unroll
        for (int hh = 0; hh < 4; hh++) {
#pragma unroll
            for (int off = 16; off > 0; off >>= 1) {
                el[hh] += __shfl_xor_sync(0xffffffffu, el[hh], off);
                er[hh] += __shfl_xor_sync(0xffffffffu, er[hh], off);
            }
        }
        if (lane == 0) {
            g_el[node] = make_float4(el[0], el[1], el[2], el[3]);
            g_er[node] = make_float4(er[0], er[1], er[2], er[3]);
        }
    }
}

// per-edge: w = exp(leaky(el[src]+er[dst])); degree histogram.
// segment_max skipped (softmax shift-invariant, |e| small); denominator folded
// into agg_kernel (sum of weights is accumulated there), so NO float atomics here.
__global__ void edge_kernel(const int* __restrict__ src, const int* __restrict__ dst) {
    int i = blockIdx.x * blockDim.x + threadIdx.x;
    int stride = gridDim.x * blockDim.x;
    for (int e = i; e < N_EDGES; e += stride) {
        int s = src[e], d = dst[e];
        float4 l = g_el[s], r = g_er[d];
        float4 x = make_float4(l.x + r.x, l.y + r.y, l.z + r.z, l.w + r.w);
        x.x = x.x > 0.f ? x.x : NEG_SLOPE * x.x;
        x.y = x.y > 0.f ? x.y : NEG_SLOPE * x.y;
        x.z = x.z > 0.f ? x.z : NEG_SLOPE * x.z;
        x.w = x.w > 0.f ? x.w : NEG_SLOPE * x.w;
        g_w[e] = make_float4(__expf(x.x), __expf(x.y), __expf(x.z), __expf(x.w));
        atomicAdd(&g_deg[d], 1);
    }
}

// 3-kernel exclusive scan of g_deg -> g_rowstart (chunks of 1024).
__global__ void scanA() {
    __shared__ int sh[1024];
    int b = blockIdx.x, t = threadIdx.x;
    int idx = b * 1024 + t;
    int v = (idx < N_NODES) ? g_deg[idx] : 0;
    sh[t] = v;
    __syncthreads();
    for (int off = 1; off < 1024; off <<= 1) {
        int add = (t >= off) ? sh[t - off] : 0;
        __syncthreads();
        sh[t] += add;
        __syncthreads();
    }
    if (idx < N_NODES) g_rowstart[idx] = sh[t] - v;
    if (t == 1023) g_blocksums[b] = sh[t];
}
__global__ void scanB(int nb) {
    __shared__ int sh[128];
    int t = threadIdx.x;
    int v = (t < nb) ? g_blocksums[t] : 0;
    sh[t] = v;
    __syncthreads();
    for (int off = 1; off < 128; off <<= 1) {
        int add = (t >= off) ? sh[t - off] : 0;
        __syncthreads();
        sh[t] += add;
        __syncthreads();
    }
    g_blockoff[t] = sh[t] - v;
}
__global__ void scanC() {
    int idx = blockIdx.x * 1024 + threadIdx.x;
    if (idx < N_NODES) g_rowstart[idx] += g_blockoff[blockIdx.x];
}

// counting-sort scatter into CSR order
__global__ void scatter_kernel(const int* __restrict__ src, const int* __restrict__ dst) {
    int i = blockIdx.x * blockDim.x + threadIdx.x;
    int stride = gridDim.x * blockDim.x;
    for (int e = i; e < N_EDGES; e += stride) {
        int d = dst[e];
        int p = g_rowstart[d] + atomicAdd(&g_cursor[d], 1);
        g_srcsorted[p] = src[e];
        g_wsorted[p] = g_w[e];
    }
}

// one warp per dst node: weight-accumulated gather of h[src] over all 256 channels
// (normalized at the end by the per-head weight sum), fused residual + bias + ELU
// + head-mean + BN partial sums.
__global__ __launch_bounds__(256) void agg_kernel(const float* __restrict__ bias) {
    __shared__ float sh_sum[64], sh_sq[64];
    if (threadIdx.x < 64) { sh_sum[threadIdx.x] = 0.f; sh_sq[threadIdx.x] = 0.f; }
    __syncthreads();
    int warp = (blockIdx.x * blockDim.x + threadIdx.x) >> 5;
    int lane = threadIdx.x & 31;
    int nw = (gridDim.x * blockDim.x) >> 5;
    const float4* bp = (const float4*)bias;

    for (int node = warp; node < N_NODES; node += nw) {
        int start = g_rowstart[node];
        int deg = g_deg[node];
        float4 accA = make_float4(0, 0, 0, 0), accB = make_float4(0, 0, 0, 0);
        float slo = 0.f, shi = 0.f;
        for (int j = 0; j < deg; j++) {
            int s = g_srcsorted[start + j];
            float4 w4 = g_wsorted[start + j];
            float alo = (lane < 16) ? w4.x : w4.y;   // channels [0,128): heads 0/1
            float ahi = (lane < 16) ? w4.z : w4.w;   // channels [128,256): heads 2/3
            slo += alo; shi += ahi;
            const float4* hp = g_h + (long)s * 64;
            float4 h0 = hp[lane];
            float4 h1 = hp[32 + lane];
            accA.x += alo * h0.x; accA.y += alo * h0.y; accA.z += alo * h0.z; accA.w += alo * h0.w;
            accB.x += ahi * h1.x; accB.y += ahi * h1.y; accB.z += ahi * h1.z; accB.w += ahi * h1.w;
        }
        float ilo = (deg > 0) ? 1.f / slo : 0.f;
        float ihi = (deg > 0) ? 1.f / shi : 0.f;
        accA.x *= ilo; accA.y *= ilo; accA.z *= ilo; accA.w *= ilo;
        accB.x *= ihi; accB.y *= ihi; accB.z *= ihi; accB.w *= ihi;
        const float4* rp = g_res + (long)node * 64;
        float4 r0 = rp[lane], r1 = rp[32 + lane];
        float4 b0 = bp[lane], b1 = bp[32 + lane];
        float4 v0, v1;
        v0.x = accA.x + r0.x + b0.x; v0.y = accA.y + r0.y + b0.y;
        v0.z = accA.z + r0.z + b0.z; v0.w = accA.w + r0.w + b0.w;
        v1.x = accB.x + r1.x + b1.x; v1.y = accB.y + r1.y + b1.y;
        v1.z = accB.z + r1.z + b1.z; v1.w = accB.w + r1.w + b1.w;
        // ELU
        v0.x = v0.x > 0.f ? v0.x : (__expf(v0.x) - 1.f);
        v0.y = v0.y > 0.f ? v0.y : (__expf(v0.y) - 1.f);
        v0.z = v0.z > 0.f ? v0.z : (__expf(v0.z) - 1.f);
        v0.w = v0.w > 0.f ? v0.w : (__expf(v0.w) - 1.f);
        v1.x = v1.x > 0.f ? v1.x : (__expf(v1.x) - 1.f);
        v1.y = v1.y > 0.f ? v1.y : (__expf(v1.y) - 1.f);
        v1.z = v1.z > 0.f ? v1.z : (__expf(v1.z) - 1.f);
        v1.w = v1.w > 0.f ? v1.w : (__expf(v1.w) - 1.f);
        // mean over heads: lane l<16 holds (head0+head2) at d=4l+k; lane l+16 holds (head1+head3)
        float4 t;
        t.x = v0.x + v1.x; t.y = v0.y + v1.y; t.z = v0.z + v1.z; t.w = v0.w + v1.w;
        float4 u;
        u.x = __shfl_down_sync(0xffffffffu, t.x, 16);
        u.y = __shfl_down_sync(0xffffffffu, t.y, 16);
        u.z = __shfl_down_sync(0xffffffffu, t.z, 16);
        u.w = __shfl_down_sync(0xffffffffu, t.w, 16);
        if (lane < 16) {
            float4 o;
            o.x = (t.x + u.x) * 0.25f; o.y = (t.y + u.y) * 0.25f;
            o.z = (t.z + u.z) * 0.25f; o.w = (t.w + u.w) * 0.25f;
            g_outpre[(long)node * 16 + lane] = o;
            int d = lane * 4;
            atomicAdd(&sh_sum[d + 0], o.x); atomicAdd(&sh_sum[d + 1], o.y);
            atomicAdd(&sh_sum[d + 2], o.z); atomicAdd(&sh_sum[d + 3], o.w);
            atomicAdd(&sh_sq[d + 0], o.x * o.x); atomicAdd(&sh_sq[d + 1], o.y * o.y);
            atomicAdd(&sh_sq[d + 2], o.z * o.z); atomicAdd(&sh_sq[d + 3], o.w * o.w);
        }
    }
    __syncthreads();
    if (threadIdx.x < 64) {
        atomicAdd(&g_bnsum[threadIdx.x], sh_sum[threadIdx.x]);
        atomicAdd(&g_bnsq[threadIdx.x], sh_sq[threadIdx.x]);
    }
}

__global__ void bn_finalize(const float* __restrict__ gamma, const float* __restrict__ beta) {
    int d = threadIdx.x;  // 64 threads
    float n = (float)N_NODES;
    float mu = g_bnsum[d] / n;
    float var = g_bnsq[d] / n - mu * mu;
    float rs = rsqrtf(var + BN_EPS);
    g_scale[d] = rs * gamma[d];
    g_shift[d] = beta[d] - mu * rs * gamma[d];
}

__global__ void norm_kernel(float* __restrict__ out) {
    int i = blockIdx.x * blockDim.x + threadIdx.x;
    int stride = gridDim.x * blockDim.x;
    const float4* sp = (const float4*)g_scale;
    const float4* hp = (const float4*)g_shift;
    float4* o4 = (float4*)out;
    for (int idx = i; idx < N_NODES * 16; idx += stride) {
        float4 v = g_outpre[idx];
        int d4 = idx & 15;
        float4 sc = sp[d4], sh = hp[d4];
        v.x = v.x * sc.x + sh.x;
        v.y = v.y * sc.y + sh.y;
        v.z = v.z * sc.z + sh.z;
        v.w = v.w * sc.w + sh.w;
        o4[idx] = v;
    }
}

// ---------------- launch ----------------
extern "C" void kernel_launch(void* const* d_in, const int* in_sizes, int n_in,
                              void* d_out, int out_size) {
    const float* feats  = (const float*)d_in[0];
    const int*   src    = (const int*)d_in[1];   // jnp.int64 is silently int32 (JAX x64 disabled)
    const int*   dst    = (const int*)d_in[2];
    const float* fc_w   = (const float*)d_in[3];
    const float* attn_l = (const float*)d_in[4];
    const float* attn_r = (const float*)d_in[5];
    const float* res_w  = (const float*)d_in[6];
    const float* bias   = (const float*)d_in[7];
    const float* gamma  = (const float*)d_in[8];
    const float* beta   = (const float*)d_in[9];
    float* out = (float*)d_out;

    zero_kernel<<<1024, 256>>>();
    gemm_kernel<<<dim3(782, 4), 256>>>(feats, fc_w, res_w);
    attn_kernel<<<1024, 256>>>(attn_l, attn_r);
    edge_kernel<<<2048, 256>>>(src, dst);
    scanA<<<98, 1024>>>();
    scanB<<<1, 128>>>(98);
    scanC<<<98, 1024>>>();
    scatter_kernel<<<2048, 256>>>(src, dst);
    agg_kernel<<<12500, 256>>>(bias);
    bn_finalize<<<1, 64>>>(gamma, beta);
    norm_kernel<<<2048, 256>>>(out);
}

// round 6
// speedup vs baseline: 1.7067x; 1.7067x over previous
#include <cuda_runtime.h>
#include <cuda_fp16.h>

#define N_NODES 100000
#define N_EDGES 1600000
#define NEG_SLOPE 0.2f
#define BN_EPS 1e-5f

// ---------------- scratch (device globals) ----------------
__device__ __half  g_hh[N_NODES * 256];     // projected feats [N,256] fp16
__device__ float   g_resf[N_NODES * 256];   // residual proj   [N,256] fp32
__device__ float4  g_el[N_NODES];           // [N,4]
__device__ float4  g_er[N_NODES];           // [N,4]
__device__ float4  g_wsorted[N_EDGES];      // dst-sorted exp weights
__device__ int     g_srcsorted[N_EDGES];    // dst-sorted src ids
__device__ int     g_deg[N_NODES];
__device__ int     g_rowstart[N_NODES];
__device__ int     g_cursor[N_NODES];
__device__ float4  g_outpre[N_NODES * 16];  // pre-BN output [N,64]
__device__ float   g_bnsum[64];
__device__ float   g_bnsq[64];
__device__ int     g_blocksums[128];
__device__ int     g_blockoff[128];
__device__ float   g_scale[64];
__device__ float   g_shift[64];

// ---------------- kernels ----------------

__global__ void zero_kernel() {
    int i = blockIdx.x * blockDim.x + threadIdx.x;
    int stride = gridDim.x * blockDim.x;
    for (int idx = i; idx < N_NODES; idx += stride) { g_deg[idx] = 0; g_cursor[idx] = 0; }
    if (i < 64) { g_bnsum[i] = 0.f; g_bnsq[i] = 0.f; }
}

// Tensor-core GEMM: C[N,512] = feats[N,128] @ [fc_w;res_w]^T via HMMA m16n8k16.
// Block: 128(m) x 128(n) tile; 8 warps as 4(m) x 2(n); per warp 32m x 64n.
// Smem rows padded to 72 halves -> conflict-free fragment loads.
#define AS_STRIDE 72
__global__ __launch_bounds__(256) void gemm_tc(const float* __restrict__ feats,
                                               const float* __restrict__ fc_w,
                                               const float* __restrict__ res_w) {
    __shared__ __half A_s[128 * AS_STRIDE];
    __shared__ __half B_s[128 * AS_STRIDE];
    int bm = blockIdx.x, bn = blockIdx.y;           // bn 0,1 -> fc_w; 2,3 -> res_w
    const float* W = (bn < 2) ? fc_w : res_w;
    int jbase = (bn & 1) * 128;
    int t = threadIdx.x;
    int wid = t >> 5, lane = t & 31;
    int wm = wid & 3, wn = wid >> 2;
    int lq = lane >> 2, lr2 = 2 * (lane & 3);

    float acc[2][8][4];
#pragma unroll
    for (int mt = 0; mt < 2; mt++)
#pragma unroll
        for (int nt = 0; nt < 8; nt++)
#pragma unroll
            for (int k = 0; k < 4; k++) acc[mt][nt][k] = 0.f;

    int lrow = t >> 1;
    int f4base = (t & 1) * 8;
    long arow = (long)bm * 128 + lrow;
    bool aok = arow < N_NODES;

    for (int ks = 0; ks < 2; ks++) {
        int k0 = ks * 64;
        const float4* ap = (const float4*)(feats + arow * 128 + k0);
        const float4* bp = (const float4*)(W + (long)(jbase + lrow) * 128 + k0);
#pragma unroll
        for (int i = 0; i < 8; i++) {
            int f4 = f4base + i;
            float4 v = aok ? ap[f4] : make_float4(0, 0, 0, 0);
            __half2* dp = (__half2*)&A_s[lrow * AS_STRIDE + f4 * 4];
            dp[0] = __floats2half2_rn(v.x, v.y);
            dp[1] = __floats2half2_rn(v.z, v.w);
        }
#pragma unroll
        for (int i = 0; i < 8; i++) {
            int f4 = f4base + i;
            float4 v = bp[f4];
            __half2* dp = (__half2*)&B_s[lrow * AS_STRIDE + f4 * 4];
            dp[0] = __floats2half2_rn(v.x, v.y);
            dp[1] = __floats2half2_rn(v.z, v.w);
        }
        __syncthreads();
#pragma unroll
        for (int kc = 0; kc < 4; kc++) {
            int kk = kc * 16 + lr2;
            unsigned b0[8], b1[8];
#pragma unroll
            for (int nt = 0; nt < 8; nt++) {
                int n = wn * 64 + nt * 8 + lq;
                b0[nt] = *(const unsigned*)&B_s[n * AS_STRIDE + kk];
                b1[nt] = *(const unsigned*)&B_s[n * AS_STRIDE + kk + 8];
            }
#pragma unroll
            for (int mt = 0; mt < 2; mt++) {
                int r = wm * 32 + mt * 16 + lq;
                unsigned a0 = *(const unsigned*)&A_s[r * AS_STRIDE + kk];
                unsigned a1 = *(const unsigned*)&A_s[(r + 8) * AS_STRIDE + kk];
                unsigned a2 = *(const unsigned*)&A_s[r * AS_STRIDE + kk + 8];
                unsigned a3 = *(const unsigned*)&A_s[(r + 8) * AS_STRIDE + kk + 8];
#pragma unroll
                for (int nt = 0; nt < 8; nt++) {
                    asm volatile(
                        "mma.sync.aligned.m16n8k16.row.col.f32.f16.f16.f32 "
                        "{%0,%1,%2,%3}, {%4,%5,%6,%7}, {%8,%9}, {%0,%1,%2,%3};\n"
                        : "+f"(acc[mt][nt][0]), "+f"(acc[mt][nt][1]),
                          "+f"(acc[mt][nt][2]), "+f"(acc[mt][nt][3])
                        : "r"(a0), "r"(a1), "r"(a2), "r"(a3), "r"(b0[nt]), "r"(b1[nt]));
                }
            }
        }
        __syncthreads();
    }

    // epilogue
#pragma unroll
    for (int mt = 0; mt < 2; mt++) {
#pragma unroll
        for (int nt = 0; nt < 8; nt++) {
            long row0 = (long)bm * 128 + wm * 32 + mt * 16 + lq;
            long row1 = row0 + 8;
            int colg = jbase + wn * 64 + nt * 8 + lr2;
            if (bn < 2) {
                if (row0 < N_NODES)
                    *(__half2*)&g_hh[row0 * 256 + colg] = __floats2half2_rn(acc[mt][nt][0], acc[mt][nt][1]);
                if (row1 < N_NODES)
                    *(__half2*)&g_hh[row1 * 256 + colg] = __floats2half2_rn(acc[mt][nt][2], acc[mt][nt][3]);
            } else {
                if (row0 < N_NODES)
                    *(float2*)&g_resf[row0 * 256 + colg] = make_float2(acc[mt][nt][0], acc[mt][nt][1]);
                if (row1 < N_NODES)
                    *(float2*)&g_resf[row1 * 256 + colg] = make_float2(acc[mt][nt][2], acc[mt][nt][3]);
            }
        }
    }
}

// el/er: one warp per node; channel block g*64 == head g.
__global__ void attn_kernel(const float* __restrict__ attn_l, const float* __restrict__ attn_r) {
    int warp = (blockIdx.x * blockDim.x + threadIdx.x) >> 5;
    int lane = threadIdx.x & 31;
    int nw = (gridDim.x * blockDim.x) >> 5;
    for (int node = warp; node < N_NODES; node += nw) {
        float el[4], er[4];
#pragma unroll
        for (int g = 0; g < 4; g++) {
            int c = g * 64 + 2 * lane;
            __half2 hv = *(const __half2*)&g_hh[(long)node * 256 + c];
            float2 f = __half22float2(hv);
            float2 al = *(const float2*)&attn_l[c];
            float2 ar = *(const float2*)&attn_r[c];
            el[g] = f.x * al.x + f.y * al.y;
            er[g] = f.x * ar.x + f.y * ar.y;
        }
#pragma unroll
        for (int g = 0; g < 4; g++) {
#pragma unroll
            for (int off = 16; off > 0; off >>= 1) {
                el[g] += __shfl_xor_sync(0xffffffffu, el[g], off);
                er[g] += __shfl_xor_sync(0xffffffffu, er[g], off);
            }
        }
        if (lane == 0) {
            g_el[node] = make_float4(el[0], el[1], el[2], el[3]);
            g_er[node] = make_float4(er[0], er[1], er[2], er[3]);
        }
    }
}

// degree histogram only
__global__ void deg_kernel(const int* __restrict__ dst) {
    int i = blockIdx.x * blockDim.x + threadIdx.x;
    int stride = gridDim.x * blockDim.x;
    for (int e = i; e < N_EDGES; e += stride) atomicAdd(&g_deg[dst[e]], 1);
}

// 3-kernel exclusive scan of g_deg -> g_rowstart (chunks of 1024).
__global__ void scanA() {
    __shared__ int sh[1024];
    int b = blockIdx.x, t = threadIdx.x;
    int idx = b * 1024 + t;
    int v = (idx < N_NODES) ? g_deg[idx] : 0;
    sh[t] = v;
    __syncthreads();
    for (int off = 1; off < 1024; off <<= 1) {
        int add = (t >= off) ? sh[t - off] : 0;
        __syncthreads();
        sh[t] += add;
        __syncthreads();
    }
    if (idx < N_NODES) g_rowstart[idx] = sh[t] - v;
    if (t == 1023) g_blocksums[b] = sh[t];
}
__global__ void scanB(int nb) {
    __shared__ int sh[128];
    int t = threadIdx.x;
    int v = (t < nb) ? g_blocksums[t] : 0;
    sh[t] = v;
    __syncthreads();
    for (int off = 1; off < 128; off <<= 1) {
        int add = (t >= off) ? sh[t - off] : 0;
        __syncthreads();
        sh[t] += add;
        __syncthreads();
    }
    g_blockoff[t] = sh[t] - v;
}
__global__ void scanC() {
    int idx = blockIdx.x * 1024 + threadIdx.x;
    if (idx < N_NODES) g_rowstart[idx] += g_blockoff[blockIdx.x];
}

// counting-sort scatter into CSR order; computes exp(leaky(el+er)) inline.
// segment_max skipped (softmax shift-invariant, logits small).
__global__ void scatter_kernel(const int* __restrict__ src, const int* __restrict__ dst) {
    int i = blockIdx.x * blockDim.x + threadIdx.x;
    int stride = gridDim.x * blockDim.x;
    for (int e = i; e < N_EDGES; e += stride) {
        int s = src[e], d = dst[e];
        float4 l = g_el[s], r = g_er[d];
        float4 x = make_float4(l.x + r.x, l.y + r.y, l.z + r.z, l.w + r.w);
        x.x = x.x > 0.f ? x.x : NEG_SLOPE * x.x;
        x.y = x.y > 0.f ? x.y : NEG_SLOPE * x.y;
        x.z = x.z > 0.f ? x.z : NEG_SLOPE * x.z;
        x.w = x.w > 0.f ? x.w : NEG_SLOPE * x.w;
        int p = g_rowstart[d] + atomicAdd(&g_cursor[d], 1);
        g_srcsorted[p] = s;
        g_wsorted[p] = make_float4(__expf(x.x), __expf(x.y), __expf(x.z), __expf(x.w));
    }
}

__device__ __forceinline__ void acc_edge(int s, float alo, float ahi, int lane,
                                         float4& accA, float4& accB) {
    const __half2* hp = (const __half2*)&g_hh[(long)s * 256];
    uint2 u0 = *(const uint2*)(hp + 2 * lane);        // channels 4*lane..+3
    uint2 u1 = *(const uint2*)(hp + 64 + 2 * lane);   // channels 128+4*lane..+3
    float2 a = __half22float2(*(__half2*)&u0.x);
    float2 b = __half22float2(*(__half2*)&u0.y);
    float2 c = __half22float2(*(__half2*)&u1.x);
    float2 d = __half22float2(*(__half2*)&u1.y);
    accA.x += alo * a.x; accA.y += alo * a.y; accA.z += alo * b.x; accA.w += alo * b.y;
    accB.x += ahi * c.x; accB.y += ahi * c.y; accB.z += ahi * d.x; accB.w += ahi * d.y;
}

// one warp per dst node: weight-accumulated gather of h[src], normalized at the
// end; fused residual + bias + ELU + head-mean + BN partial sums.
__global__ __launch_bounds__(256) void agg_kernel(const float* __restrict__ bias) {
    __shared__ float sh_sum[64], sh_sq[64];
    if (threadIdx.x < 64) { sh_sum[threadIdx.x] = 0.f; sh_sq[threadIdx.x] = 0.f; }
    __syncthreads();
    int warp = (blockIdx.x * blockDim.x + threadIdx.x) >> 5;
    int lane = threadIdx.x & 31;
    int nw = (gridDim.x * blockDim.x) >> 5;
    const float4* bp = (const float4*)bias;
    bool lo16 = lane < 16;

    for (int node = warp; node < N_NODES; node += nw) {
        int start = g_rowstart[node];
        int deg = g_deg[node];
        float4 accA = make_float4(0, 0, 0, 0), accB = make_float4(0, 0, 0, 0);
        float slo = 0.f, shi = 0.f;
        int j = 0;
        for (; j + 1 < deg; j += 2) {
            int s0 = g_srcsorted[start + j];
            int s1 = g_srcsorted[start + j + 1];
            float4 w0 = g_wsorted[start + j];
            float4 w1 = g_wsorted[start + j + 1];
            float alo0 = lo16 ? w0.x : w0.y, ahi0 = lo16 ? w0.z : w0.w;
            float alo1 = lo16 ? w1.x : w1.y, ahi1 = lo16 ? w1.z : w1.w;
            slo += alo0 + alo1; shi += ahi0 + ahi1;
            acc_edge(s0, alo0, ahi0, lane, accA, accB);
            acc_edge(s1, alo1, ahi1, lane, accA, accB);
        }
        if (j < deg) {
            int s0 = g_srcsorted[start + j];
            float4 w0 = g_wsorted[start + j];
            float alo0 = lo16 ? w0.x : w0.y, ahi0 = lo16 ? w0.z : w0.w;
            slo += alo0; shi += ahi0;
            acc_edge(s0, alo0, ahi0, lane, accA, accB);
        }
        float ilo = (deg > 0) ? 1.f / slo : 0.f;
        float ihi = (deg > 0) ? 1.f / shi : 0.f;
        accA.x *= ilo; accA.y *= ilo; accA.z *= ilo; accA.w *= ilo;
        accB.x *= ihi; accB.y *= ihi; accB.z *= ihi; accB.w *= ihi;

        const float4* rp = (const float4*)&g_resf[(long)node * 256];
        float4 r0 = rp[lane], r1 = rp[32 + lane];
        float4 b0 = bp[lane], b1 = bp[32 + lane];
        float4 v0, v1;
        v0.x = accA.x + r0.x + b0.x; v0.y = accA.y + r0.y + b0.y;
        v0.z = accA.z + r0.z + b0.z; v0.w = accA.w + r0.w + b0.w;
        v1.x = accB.x + r1.x + b1.x; v1.y = accB.y + r1.y + b1.y;
        v1.z = accB.z + r1.z + b1.z; v1.w = accB.w + r1.w + b1.w;
        v0.x = v0.x > 0.f ? v0.x : (__expf(v0.x) - 1.f);
        v0.y = v0.y > 0.f ? v0.y : (__expf(v0.y) - 1.f);
        v0.z = v0.z > 0.f ? v0.z : (__expf(v0.z) - 1.f);
        v0.w = v0.w > 0.f ? v0.w : (__expf(v0.w) - 1.f);
        v1.x = v1.x > 0.f ? v1.x : (__expf(v1.x) - 1.f);
        v1.y = v1.y > 0.f ? v1.y : (__expf(v1.y) - 1.f);
        v1.z = v1.z > 0.f ? v1.z : (__expf(v1.z) - 1.f);
        v1.w = v1.w > 0.f ? v1.w : (__expf(v1.w) - 1.f);
        float4 t;
        t.x = v0.x + v1.x; t.y = v0.y + v1.y; t.z = v0.z + v1.z; t.w = v0.w + v1.w;
        float4 u;
        u.x = __shfl_down_sync(0xffffffffu, t.x, 16);
        u.y = __shfl_down_sync(0xffffffffu, t.y, 16);
        u.z = __shfl_down_sync(0xffffffffu, t.z, 16);
        u.w = __shfl_down_sync(0xffffffffu, t.w, 16);
        if (lo16) {
            float4 o;
            o.x = (t.x + u.x) * 0.25f; o.y = (t.y + u.y) * 0.25f;
            o.z = (t.z + u.z) * 0.25f; o.w = (t.w + u.w) * 0.25f;
            g_outpre[(long)node * 16 + lane] = o;
            int d = lane * 4;
            atomicAdd(&sh_sum[d + 0], o.x); atomicAdd(&sh_sum[d + 1], o.y);
            atomicAdd(&sh_sum[d + 2], o.z); atomicAdd(&sh_sum[d + 3], o.w);
            atomicAdd(&sh_sq[d + 0], o.x * o.x); atomicAdd(&sh_sq[d + 1], o.y * o.y);
            atomicAdd(&sh_sq[d + 2], o.z * o.z); atomicAdd(&sh_sq[d + 3], o.w * o.w);
        }
    }
    __syncthreads();
    if (threadIdx.x < 64) {
        atomicAdd(&g_bnsum[threadIdx.x], sh_sum[threadIdx.x]);
        atomicAdd(&g_bnsq[threadIdx.x], sh_sq[threadIdx.x]);
    }
}

__global__ void bn_finalize(const float* __restrict__ gamma, const float* __restrict__ beta) {
    int d = threadIdx.x;
    float n = (float)N_NODES;
    float mu = g_bnsum[d] / n;
    float var = g_bnsq[d] / n - mu * mu;
    float rs = rsqrtf(var + BN_EPS);
    g_scale[d] = rs * gamma[d];
    g_shift[d] = beta[d] - mu * rs * gamma[d];
}

__global__ void norm_kernel(float* __restrict__ out) {
    int i = blockIdx.x * blockDim.x + threadIdx.x;
    int stride = gridDim.x * blockDim.x;
    const float4* sp = (const float4*)g_scale;
    const float4* hp = (const float4*)g_shift;
    float4* o4 = (float4*)out;
    for (int idx = i; idx < N_NODES * 16; idx += stride) {
        float4 v = g_outpre[idx];
        int d4 = idx & 15;
        float4 sc = sp[d4], sh = hp[d4];
        v.x = v.x * sc.x + sh.x;
        v.y = v.y * sc.y + sh.y;
        v.z = v.z * sc.z + sh.z;
        v.w = v.w * sc.w + sh.w;
        o4[idx] = v;
    }
}

// ---------------- launch ----------------
extern "C" void kernel_launch(void* const* d_in, const int* in_sizes, int n_in,
                              void* d_out, int out_size) {
    const float* feats  = (const float*)d_in[0];
    const int*   src    = (const int*)d_in[1];   // jnp "int64" is int32 (x64 disabled)
    const int*   dst    = (const int*)d_in[2];
    const float* fc_w   = (const float*)d_in[3];
    const float* attn_l = (const float*)d_in[4];
    const float* attn_r = (const float*)d_in[5];
    const float* res_w  = (const float*)d_in[6];
    const float* bias   = (const float*)d_in[7];
    const float* gamma  = (const float*)d_in[8];
    const float* beta   = (const float*)d_in[9];
    float* out = (float*)d_out;

    zero_kernel<<<1024, 256>>>();
    gemm_tc<<<dim3(782, 4), 256>>>(feats, fc_w, res_w);
    attn_kernel<<<1024, 256>>>(attn_l, attn_r);
    deg_kernel<<<1024, 256>>>(dst);
    scanA<<<98, 1024>>>();
    scanB<<<1, 128>>>(98);
    scanC<<<98, 1024>>>();
    scatter_kernel<<<2048, 256>>>(src, dst);
    agg_kernel<<<12500, 256>>>(bias);
    bn_finalize<<<1, 64>>>(gamma, beta);
    norm_kernel<<<2048, 256>>>(out);
}

// round 8
// speedup vs baseline: 1.9505x; 1.1428x over previous
#include <cuda_runtime.h>
#include <cuda_fp16.h>

#define N_NODES 100000
#define N_EDGES 1600000
#define NEG_SLOPE 0.2f
#define BN_EPS 1e-5f

// ---------------- scratch (device globals) ----------------
__device__ __half  g_hh[N_NODES * 256];     // projected feats [N,256] fp16
__device__ __half  g_resh[N_NODES * 256];   // residual proj   [N,256] fp16
__device__ float4  g_el[N_NODES];           // [N,4]
__device__ float4  g_er[N_NODES];           // [N,4]
__device__ float4  g_wsorted[N_EDGES];      // dst-sorted exp weights
__device__ int     g_srcsorted[N_EDGES];    // dst-sorted src ids
__device__ int     g_deg[N_NODES];
__device__ int     g_rowstart[N_NODES];
__device__ int     g_cursor[N_NODES];
__device__ float4  g_outpre[N_NODES * 16];  // pre-BN output [N,64]
__device__ float   g_bnsum[64];
__device__ float   g_bnsq[64];
__device__ int     g_blocksums[128];
__device__ int     g_blockoff[128];

// ---------------- kernels ----------------

__global__ void zero_kernel() {
    int i = blockIdx.x * blockDim.x + threadIdx.x;
    int stride = gridDim.x * blockDim.x;
    for (int idx = i; idx < N_NODES; idx += stride) { g_deg[idx] = 0; g_cursor[idx] = 0; }
    if (i < 64) { g_bnsum[i] = 0.f; g_bnsq[i] = 0.f; }
}

// Fused tensor-core GEMM: one block per 128-row stripe computes all 512 output
// cols (fc 256 + res 256), A tile resident in smem across the 4 weight tiles.
// el/er attention dots fused into the fc epilogues (each warp's 64-col slice is
// exactly one head). A stride 136 halves (68 words, ≡4 mod 32 -> conflict-free).
#define A_STRIDE 136
#define B_STRIDE 72
#define SMEM_A_OFF 0
#define SMEM_B_OFF 34816
#define SMEM_EL_OFF 53248
#define SMEM_ER_OFF 55296
#define SMEM_GEMM 57344
__global__ __launch_bounds__(256) void gemm_tc(const float* __restrict__ feats,
                                               const float* __restrict__ fc_w,
                                               const float* __restrict__ res_w,
                                               const float* __restrict__ attn_l,
                                               const float* __restrict__ attn_r) {
    extern __shared__ char smem[];
    __half* A_s = (__half*)(smem + SMEM_A_OFF);
    __half* B_s = (__half*)(smem + SMEM_B_OFF);
    float*  el_s = (float*)(smem + SMEM_EL_OFF);   // [128][4]
    float*  er_s = (float*)(smem + SMEM_ER_OFF);   // [128][4]

    int bm = blockIdx.x;
    int t = threadIdx.x;
    int wid = t >> 5, lane = t & 31;
    int wm = wid & 3, wn = wid >> 2;
    int lq = lane >> 2, lr2 = 2 * (lane & 3);
    int lrow = t >> 1;

    // load full A tile (128 rows x 128 k) once, fp32 -> fp16
    {
        long arow = (long)bm * 128 + lrow;
        bool aok = arow < N_NODES;
        const float4* ap = (const float4*)(feats + arow * 128);
#pragma unroll
        for (int i = 0; i < 16; i++) {
            int f4 = (t & 1) * 16 + i;
            float4 v = aok ? ap[f4] : make_float4(0, 0, 0, 0);
            __half2* dp = (__half2*)&A_s[lrow * A_STRIDE + f4 * 4];
            dp[0] = __floats2half2_rn(v.x, v.y);
            dp[1] = __floats2half2_rn(v.z, v.w);
        }
    }
    __syncthreads();

    for (int cc = 0; cc < 4; cc++) {
        const float* W = (cc < 2) ? fc_w : res_w;
        int jbase = (cc & 1) * 128;

        float acc[2][8][4];
#pragma unroll
        for (int mt = 0; mt < 2; mt++)
#pragma unroll
            for (int nt = 0; nt < 8; nt++)
#pragma unroll
                for (int k = 0; k < 4; k++) acc[mt][nt][k] = 0.f;

        for (int ks = 0; ks < 2; ks++) {
            // load B chunk: 128 out-cols x 64 k
            {
                const float4* bp = (const float4*)(W + (long)(jbase + lrow) * 128 + ks * 64);
#pragma unroll
                for (int i = 0; i < 8; i++) {
                    int f4 = (t & 1) * 8 + i;
                    float4 v = bp[f4];
                    __half2* dp = (__half2*)&B_s[lrow * B_STRIDE + f4 * 4];
                    dp[0] = __floats2half2_rn(v.x, v.y);
                    dp[1] = __floats2half2_rn(v.z, v.w);
                }
            }
            __syncthreads();
#pragma unroll
            for (int kc4 = 0; kc4 < 4; kc4++) {
                int kkA = (ks * 4 + kc4) * 16 + lr2;
                int kkB = kc4 * 16 + lr2;
                unsigned b0[8], b1[8];
#pragma unroll
                for (int nt = 0; nt < 8; nt++) {
                    int n = wn * 64 + nt * 8 + lq;
                    b0[nt] = *(const unsigned*)&B_s[n * B_STRIDE + kkB];
                    b1[nt] = *(const unsigned*)&B_s[n * B_STRIDE + kkB + 8];
                }
#pragma unroll
                for (int mt = 0; mt < 2; mt++) {
                    int r = wm * 32 + mt * 16 + lq;
                    unsigned a0 = *(const unsigned*)&A_s[r * A_STRIDE + kkA];
                    unsigned a1 = *(const unsigned*)&A_s[(r + 8) * A_STRIDE + kkA];
                    unsigned a2 = *(const unsigned*)&A_s[r * A_STRIDE + kkA + 8];
                    unsigned a3 = *(const unsigned*)&A_s[(r + 8) * A_STRIDE + kkA + 8];
#pragma unroll
                    for (int nt = 0; nt < 8; nt++) {
                        asm volatile(
                            "mma.sync.aligned.m16n8k16.row.col.f32.f16.f16.f32 "
                            "{%0,%1,%2,%3}, {%4,%5,%6,%7}, {%8,%9}, {%0,%1,%2,%3};\n"
                            : "+f"(acc[mt][nt][0]), "+f"(acc[mt][nt][1]),
                              "+f"(acc[mt][nt][2]), "+f"(acc[mt][nt][3])
                            : "r"(a0), "r"(a1), "r"(a2), "r"(a3), "r"(b0[nt]), "r"(b1[nt]));
                    }
                }
            }
            __syncthreads();
        }

        // epilogue: store tile (fp16), plus el/er partials for fc tiles
        __half* outp = (cc < 2) ? g_hh : g_resh;
        int head = cc * 2 + wn;  // valid for cc<2
#pragma unroll
        for (int mt = 0; mt < 2; mt++) {
            long r0g = (long)bm * 128 + wm * 32 + mt * 16 + lq;
            long r1g = r0g + 8;
            float pl0 = 0.f, pl1 = 0.f, pr0 = 0.f, pr1 = 0.f;
#pragma unroll
            for (int nt = 0; nt < 8; nt++) {
                int colg = jbase + wn * 64 + nt * 8 + lr2;
                if (r0g < N_NODES)
                    *(__half2*)&outp[r0g * 256 + colg] = __floats2half2_rn(acc[mt][nt][0], acc[mt][nt][1]);
                if (r1g < N_NODES)
                    *(__half2*)&outp[r1g * 256 + colg] = __floats2half2_rn(acc[mt][nt][2], acc[mt][nt][3]);
                if (cc < 2) {
                    float al0 = attn_l[colg], al1 = attn_l[colg + 1];
                    float ar0 = attn_r[colg], ar1 = attn_r[colg + 1];
                    pl0 += acc[mt][nt][0] * al0 + acc[mt][nt][1] * al1;
                    pl1 += acc[mt][nt][2] * al0 + acc[mt][nt][3] * al1;
                    pr0 += acc[mt][nt][0] * ar0 + acc[mt][nt][1] * ar1;
                    pr1 += acc[mt][nt][2] * ar0 + acc[mt][nt][3] * ar1;
                }
            }
            if (cc < 2) {
                // reduce across the 4-lane quad (same lq)
#pragma unroll
                for (int off = 1; off < 4; off <<= 1) {
                    pl0 += __shfl_xor_sync(0xffffffffu, pl0, off);
                    pl1 += __shfl_xor_sync(0xffffffffu, pl1, off);
                    pr0 += __shfl_xor_sync(0xffffffffu, pr0, off);
                    pr1 += __shfl_xor_sync(0xffffffffu, pr1, off);
                }
                if ((lane & 3) == 0) {
                    int rloc = wm * 32 + mt * 16 + lq;
                    el_s[rloc * 4 + head] = pl0;
                    el_s[(rloc + 8) * 4 + head] = pl1;
                    er_s[rloc * 4 + head] = pr0;
                    er_s[(rloc + 8) * 4 + head] = pr1;
                }
            }
        }
    }
    __syncthreads();
    if (t < 128) {
        long row = (long)bm * 128 + t;
        if (row < N_NODES) {
            g_el[row] = *(float4*)&el_s[t * 4];
            g_er[row] = *(float4*)&er_s[t * 4];
        }
    }
}

// degree histogram only
__global__ void deg_kernel(const int* __restrict__ dst) {
    int i = blockIdx.x * blockDim.x + threadIdx.x;
    int stride = gridDim.x * blockDim.x;
    for (int e = i; e < N_EDGES; e += stride) atomicAdd(&g_deg[dst[e]], 1);
}

// 3-kernel exclusive scan of g_deg -> g_rowstart (chunks of 1024).
__global__ void scanA() {
    __shared__ int sh[1024];
    int b = blockIdx.x, t = threadIdx.x;
    int idx = b * 1024 + t;
    int v = (idx < N_NODES) ? g_deg[idx] : 0;
    sh[t] = v;
    __syncthreads();
    for (int off = 1; off < 1024; off <<= 1) {
        int add = (t >= off) ? sh[t - off] : 0;
        __syncthreads();
        sh[t] += add;
        __syncthreads();
    }
    if (idx < N_NODES) g_rowstart[idx] = sh[t] - v;
    if (t == 1023) g_blocksums[b] = sh[t];
}
__global__ void scanB(int nb) {
    __shared__ int sh[128];
    int t = threadIdx.x;
    int v = (t < nb) ? g_blocksums[t] : 0;
    sh[t] = v;
    __syncthreads();
    for (int off = 1; off < 128; off <<= 1) {
        int add = (t >= off) ? sh[t - off] : 0;
        __syncthreads();
        sh[t] += add;
        __syncthreads();
    }
    g_blockoff[t] = sh[t] - v;
}
__global__ void scanC() {
    int idx = blockIdx.x * 1024 + threadIdx.x;
    if (idx < N_NODES) g_rowstart[idx] += g_blockoff[blockIdx.x];
}

// counting-sort scatter into CSR order; computes exp(leaky(el+er)) inline.
// segment_max skipped (softmax shift-invariant, logits small).
__global__ void scatter_kernel(const int* __restrict__ src, const int* __restrict__ dst) {
    int i = blockIdx.x * blockDim.x + threadIdx.x;
    int stride = gridDim.x * blockDim.x;
    for (int e = i; e < N_EDGES; e += stride) {
        int s = src[e], d = dst[e];
        float4 l = g_el[s], r = g_er[d];
        float4 x = make_float4(l.x + r.x, l.y + r.y, l.z + r.z, l.w + r.w);
        x.x = x.x > 0.f ? x.x : NEG_SLOPE * x.x;
        x.y = x.y > 0.f ? x.y : NEG_SLOPE * x.y;
        x.z = x.z > 0.f ? x.z : NEG_SLOPE * x.z;
        x.w = x.w > 0.f ? x.w : NEG_SLOPE * x.w;
        int p = g_rowstart[d] + atomicAdd(&g_cursor[d], 1);
        g_srcsorted[p] = s;
        g_wsorted[p] = make_float4(__expf(x.x), __expf(x.y), __expf(x.z), __expf(x.w));
    }
}

__device__ __forceinline__ void acc_edge(int s, float alo, float ahi, int lane,
                                         float4& accA, float4& accB) {
    const __half2* hp = (const __half2*)&g_hh[(long)s * 256];
    uint2 u0 = *(const uint2*)(hp + 2 * lane);        // channels 4*lane..+3
    uint2 u1 = *(const uint2*)(hp + 64 + 2 * lane);   // channels 128+4*lane..+3
    float2 a = __half22float2(*(__half2*)&u0.x);
    float2 b = __half22float2(*(__half2*)&u0.y);
    float2 c = __half22float2(*(__half2*)&u1.x);
    float2 d = __half22float2(*(__half2*)&u1.y);
    accA.x += alo * a.x; accA.y += alo * a.y; accA.z += alo * b.x; accA.w += alo * b.y;
    accB.x += ahi * c.x; accB.y += ahi * c.y; accB.z += ahi * d.x; accB.w += ahi * d.y;
}

// one warp per dst node: weight-accumulated gather of h[src], normalized at the
// end; fused residual + bias + ELU + head-mean + BN partial sums.
__global__ __launch_bounds__(256) void agg_kernel(const float* __restrict__ bias) {
    __shared__ float sh_sum[64], sh_sq[64];
    if (threadIdx.x < 64) { sh_sum[threadIdx.x] = 0.f; sh_sq[threadIdx.x] = 0.f; }
    __syncthreads();
    int warp = (blockIdx.x * blockDim.x + threadIdx.x) >> 5;
    int lane = threadIdx.x & 31;
    int nw = (gridDim.x * blockDim.x) >> 5;
    const float4* bp = (const float4*)bias;
    bool lo16 = lane < 16;

    for (int node = warp; node < N_NODES; node += nw) {
        int start = g_rowstart[node];
        int deg = g_deg[node];
        float4 accA = make_float4(0, 0, 0, 0), accB = make_float4(0, 0, 0, 0);
        float slo = 0.f, shi = 0.f;
        int j = 0;
        for (; j + 1 < deg; j += 2) {
            int s0 = g_srcsorted[start + j];
            int s1 = g_srcsorted[start + j + 1];
            float4 w0 = g_wsorted[start + j];
            float4 w1 = g_wsorted[start + j + 1];
            float alo0 = lo16 ? w0.x : w0.y, ahi0 = lo16 ? w0.z : w0.w;
            float alo1 = lo16 ? w1.x : w1.y, ahi1 = lo16 ? w1.z : w1.w;
            slo += alo0 + alo1; shi += ahi0 + ahi1;
            acc_edge(s0, alo0, ahi0, lane, accA, accB);
            acc_edge(s1, alo1, ahi1, lane, accA, accB);
        }
        if (j < deg) {
            int s0 = g_srcsorted[start + j];
            float4 w0 = g_wsorted[start + j];
            float alo0 = lo16 ? w0.x : w0.y, ahi0 = lo16 ? w0.z : w0.w;
            slo += alo0; shi += ahi0;
            acc_edge(s0, alo0, ahi0, lane, accA, accB);
        }
        float ilo = (deg > 0) ? 1.f / slo : 0.f;
        float ihi = (deg > 0) ? 1.f / shi : 0.f;
        accA.x *= ilo; accA.y *= ilo; accA.z *= ilo; accA.w *= ilo;
        accB.x *= ihi; accB.y *= ihi; accB.z *= ihi; accB.w *= ihi;

        // residual (fp16) for this node's channels
        const __half2* rp = (const __half2*)&g_resh[(long)node * 256];
        uint2 q0 = *(const uint2*)(rp + 2 * lane);
        uint2 q1 = *(const uint2*)(rp + 64 + 2 * lane);
        float2 ra = __half22float2(*(__half2*)&q0.x);
        float2 rb = __half22float2(*(__half2*)&q0.y);
        float2 rc = __half22float2(*(__half2*)&q1.x);
        float2 rd = __half22float2(*(__half2*)&q1.y);
        float4 b0 = bp[lane], b1 = bp[32 + lane];
        float4 v0, v1;
        v0.x = accA.x + ra.x + b0.x; v0.y = accA.y + ra.y + b0.y;
        v0.z = accA.z + rb.x + b0.z; v0.w = accA.w + rb.y + b0.w;
        v1.x = accB.x + rc.x + b1.x; v1.y = accB.y + rc.y + b1.y;
        v1.z = accB.z + rd.x + b1.z; v1.w = accB.w + rd.y + b1.w;
        v0.x = v0.x > 0.f ? v0.x : (__expf(v0.x) - 1.f);
        v0.y = v0.y > 0.f ? v0.y : (__expf(v0.y) - 1.f);
        v0.z = v0.z > 0.f ? v0.z : (__expf(v0.z) - 1.f);
        v0.w = v0.w > 0.f ? v0.w : (__expf(v0.w) - 1.f);
        v1.x = v1.x > 0.f ? v1.x : (__expf(v1.x) - 1.f);
        v1.y = v1.y > 0.f ? v1.y : (__expf(v1.y) - 1.f);
        v1.z = v1.z > 0.f ? v1.z : (__expf(v1.z) - 1.f);
        v1.w = v1.w > 0.f ? v1.w : (__expf(v1.w) - 1.f);
        float4 t;
        t.x = v0.x + v1.x; t.y = v0.y + v1.y; t.z = v0.z + v1.z; t.w = v0.w + v1.w;
        float4 u;
        u.x = __shfl_down_sync(0xffffffffu, t.x, 16);
        u.y = __shfl_down_sync(0xffffffffu, t.y, 16);
        u.z = __shfl_down_sync(0xffffffffu, t.z, 16);
        u.w = __shfl_down_sync(0xffffffffu, t.w, 16);
        if (lo16) {
            float4 o;
            o.x = (t.x + u.x) * 0.25f; o.y = (t.y + u.y) * 0.25f;
            o.z = (t.z + u.z) * 0.25f; o.w = (t.w + u.w) * 0.25f;
            g_outpre[(long)node * 16 + lane] = o;
            int d = lane * 4;
            atomicAdd(&sh_sum[d + 0], o.x); atomicAdd(&sh_sum[d + 1], o.y);
            atomicAdd(&sh_sum[d + 2], o.z); atomicAdd(&sh_sum[d + 3], o.w);
            atomicAdd(&sh_sq[d + 0], o.x * o.x); atomicAdd(&sh_sq[d + 1], o.y * o.y);
            atomicAdd(&sh_sq[d + 2], o.z * o.z); atomicAdd(&sh_sq[d + 3], o.w * o.w);
        }
    }
    __syncthreads();
    if (threadIdx.x < 64) {
        atomicAdd(&g_bnsum[threadIdx.x], sh_sum[threadIdx.x]);
        atomicAdd(&g_bnsq[threadIdx.x], sh_sq[threadIdx.x]);
    }
}

// BN finalize (per-block recompute) + normalize + write out
__global__ void norm_kernel(const float* __restrict__ gamma, const float* __restrict__ beta,
                            float* __restrict__ out) {
    __shared__ float sc_s[64], sh_s[64];
    if (threadIdx.x < 64) {
        int d = threadIdx.x;
        float n = (float)N_NODES;
        float mu = g_bnsum[d] / n;
        float var = g_bnsq[d] / n - mu * mu;
        float rs = rsqrtf(var + BN_EPS);
        sc_s[d] = rs * gamma[d];
        sh_s[d] = beta[d] - mu * rs * gamma[d];
    }
    __syncthreads();
    int i = blockIdx.x * blockDim.x + threadIdx.x;
    int stride = gridDim.x * blockDim.x;
    const float4* sp = (const float4*)sc_s;
    const float4* hp = (const float4*)sh_s;
    float4* o4 = (float4*)out;
    for (int idx = i; idx < N_NODES * 16; idx += stride) {
        float4 v = g_outpre[idx];
        int d4 = idx & 15;
        float4 sc = sp[d4], sh = hp[d4];
        v.x = v.x * sc.x + sh.x;
        v.y = v.y * sc.y + sh.y;
        v.z = v.z * sc.z + sh.z;
        v.w = v.w * sc.w + sh.w;
        o4[idx] = v;
    }
}

// ---------------- launch ----------------
extern "C" void kernel_launch(void* const* d_in, const int* in_sizes, int n_in,
                              void* d_out, int out_size) {
    const float* feats  = (const float*)d_in[0];
    const int*   src    = (const int*)d_in[1];   // jnp "int64" is int32 (x64 disabled)
    const int*   dst    = (const int*)d_in[2];
    const float* fc_w   = (const float*)d_in[3];
    const float* attn_l = (const float*)d_in[4];
    const float* attn_r = (const float*)d_in[5];
    const float* res_w  = (const float*)d_in[6];
    const float* bias   = (const float*)d_in[7];
    const float* gamma  = (const float*)d_in[8];
    const float* beta   = (const float*)d_in[9];
    float* out = (float*)d_out;

    cudaFuncSetAttribute(gemm_tc, cudaFuncAttributeMaxDynamicSharedMemorySize, SMEM_GEMM);

    zero_kernel<<<1024, 256>>>();
    gemm_tc<<<782, 256, SMEM_GEMM>>>(feats, fc_w, res_w, attn_l, attn_r);
    deg_kernel<<<1024, 256>>>(dst);
    scanA<<<98, 1024>>>();
    scanB<<<1, 128>>>(98);
    scanC<<<98, 1024>>>();
    scatter_kernel<<<2048, 256>>>(src, dst);
    agg_kernel<<<12500, 256>>>(bias);
    norm_kernel<<<2048, 256>>>(gamma, beta, out);
}